// round 10
// baseline (speedup 1.0000x reference)
#include <cuda_runtime.h>

// ---------------- problem constants ----------------
#define NROWS     2048
#define RROWS     4          // batch rows per CTA (1 row per thread)
#define NTHREADS  1024
#define SPONGE_N  1024
#define HALFW     512
#define QUARTW    256
#define ACT_N     256
#define DEPTH_N   8
#define BDEPTH_N  10
#define BF_SIZE   3072
#define BF_HALF   1536
#define BF_QUART  768
#define BF_DEPTH  12

#define SP_STRIDE   4624                 // >= isp(1023)+4, 16B aligned
#define MEM_OFF     (2*SP_STRIDE)        // 9248
#define BF_STRIDE   13840                // >= ibf(3071)+4
#define SMEM_FLOATS (2*BF_STRIDE)        // 27680 floats = 110720 B -> 2 CTAs/SM

// ---------------- precomputed tables ----------------
__device__ __align__(16) float2 g_rot  [DEPTH_N*BDEPTH_N*HALFW];  // sponge (cos,sin)
__device__ __align__(16) float2 g_bfrot[BF_DEPTH*BF_HALF];        // final butterfly
__device__ float4 g_act  [DEPTH_N*ACT_N];           // (bias, c, t, 1/c)
__device__ int    g_recall[DEPTH_N*ACT_N];
__device__ int    g_outidx[2048];

__global__ void prep_kernel(const float* __restrict__ angles,
                            const float* __restrict__ bf_angles,
                            const float* __restrict__ act_bias,
                            const float* __restrict__ act_curv,
                            const void*  __restrict__ recall_raw,
                            const void*  __restrict__ out_raw)
{
    int i = blockIdx.x * blockDim.x + threadIdx.x;
    const int NROT = DEPTH_N*BDEPTH_N*HALFW;       // 40960
    const int NBF  = BF_DEPTH*BF_HALF;             // 18432
    if (i < NROT) {
        float s, c; sincosf(angles[i], &s, &c);
        g_rot[i] = make_float2(c, s);
    } else if (i < NROT + NBF) {
        int j = i - NROT;
        float s, c; sincosf(bf_angles[j], &s, &c);
        g_bfrot[j] = make_float2(c, s);
    } else if (i < NROT + NBF + DEPTH_N*ACT_N) {
        int k = i - NROT - NBF;
        float cu = act_curv[k];
        float c  = 0.5f*(cu + sqrtf(cu*cu + 1.0f));
        g_act[k] = make_float4(act_bias[k], c, 0.25f*3.14159265358979323846f/c, 1.0f/c);
    }
    // dtype-robust index decode (int32 vs int64)
    if (i < 2048) {
        const int* o32 = (const int*)out_raw;
        bool is64 = (o32[1]==0 && o32[3]==0 && o32[5]==0 && o32[7]==0);
        if (is64) {
            g_outidx[i] = (int)((const long long*)out_raw)[i];
            g_recall[i] = (int)((const long long*)recall_raw)[i];
        } else {
            g_outidx[i] = o32[i];
            g_recall[i] = ((const int*)recall_raw)[i];
        }
    }
}

// ---------------- padded shared-memory indexing (row r at +r) ----------------
__device__ __forceinline__ int isp(int p) { return 4*p + ((p>>3)<<2) + ((p>>9)<<4); }
__device__ __forceinline__ int ibf(int p) { return 4*p + ((p>>3)<<2) + ((p>=1536)?16:0); }

// fixed offsets (verified constant across valid base positions; same as R5/R9)
#define SR1 576
#define SR2 1152
#define SR3 1728
#define SW1 4
#define SW2 2320
#define SW3 2324
#define BR1 1728
#define BR2 3456
#define BR3 5184
#define BW1 4
#define BW2 6928
#define BW3 6932

__device__ __forceinline__ float actf(float x, float c, float tt, float invc) {
    const float OOS2 = 0.70710678118654752f;
    float r = invc*(OOS2 - __cosf(0.78539816339744831f + c*x));
    if (x >  tt) r = invc*OOS2 + (x - tt);
    if (x < -tt) r = invc*(OOS2 - 1.0f);
    return r;
}

__global__ void __launch_bounds__(NTHREADS, 2)
sponge_kernel(const float* __restrict__ X,
              const float* __restrict__ scales,
              float* __restrict__ out)
{
    extern __shared__ float sb[];
    const int t    = threadIdx.x;
    const int row0 = blockIdx.x * RROWS;
    float* const MEMB = sb + MEM_OFF;

    // ---- load X * scales into sponge buffer 0 (thread = one position, 4 rows) ----
    {
        float sc = scales[t];
        int i0 = isp(t);
        #pragma unroll
        for (int r = 0; r < RROWS; r++)
            sb[i0 + r] = X[(size_t)(row0 + r) * SPONGE_N + t] * sc;
    }
    __syncthreads();

    // ---- per-thread constants ----
    // butterfly: thread = (pair m in [0,256), row r4 in [0,4))
    const int m   = t >> 2;
    const int r4  = t & 3;
    const int A1  = (m >> 1) + (m & 1) * HALFW;
    const int rb  = isp(A1)  + r4;       // scalar read base
    const int wb  = isp(2*m) + r4;       // scalar write base
    // act phase: thread = (position p2 in [0,512), row-half rh2)
    const int p2  = t >> 1;
    const int rh2 = t & 1;

    int cur = 0;
    for (int d = 0; d < DEPTH_N; d++) {
        // ---- 10 butterfly layers as 5 fused double-layers (R5 math, scalar) ----
        const float2* rotd = g_rot + d*(BDEPTH_N*HALFW);
        #pragma unroll
        for (int s5 = 0; s5 < BDEPTH_N/2; s5++) {
            const float2* r0 = rotd + (2*s5)*HALFW;
            float2 cs1 = r0[m];
            float2 cs2 = r0[m + QUARTW];
            float4 co4 = ((const float4*)(rotd + (2*s5+1)*HALFW))[m];
            const float* IN  = sb + cur*SP_STRIDE;
            float*       OUT = sb + (cur^1)*SP_STRIDE;

            float a1 = IN[rb];
            float a2 = IN[rb + SR1];
            float b1 = IN[rb + SR2];
            float b2 = IN[rb + SR3];
            float y1e = cs1.x*a1 + cs1.y*b1;
            float y1o = cs1.x*b1 - cs1.y*a1;
            float y2e = cs2.x*a2 + cs2.y*b2;
            float y2o = cs2.x*b2 - cs2.y*a2;
            OUT[wb]       = co4.x*y1e + co4.y*y2e;
            OUT[wb + SW1] = co4.z*y1o + co4.w*y2o;
            OUT[wb + SW2] = co4.x*y2e - co4.y*y1e;
            OUT[wb + SW3] = co4.z*y2o - co4.w*y1o;
            cur ^= 1;
            __syncthreads();
        }

        // ---- activation / mem store / recall: ONE barrier (R9-proven, float2) ----
        {
            const float* S    = sb + cur*SP_STRIDE;
            float*       OUTB = sb + (cur^1)*SP_STRIDE;
            int ja = p2 >> 1;
            float4 ap = g_act[d*ACT_N + ja];
            float2 x  = *(const float2*)(S + isp(HALFW + ja) + 2*rh2);
            float sg  = (p2 & 1) ? -1.0f : 1.0f;
            float2 o;
            o.x = actf(sg*(x.x + ap.x), ap.y, ap.z, ap.w);
            o.y = actf(sg*(x.y + ap.x), ap.y, ap.z, ap.w);

            float2 mv = *(const float2*)(S + isp(p2) + 2*rh2);
            *(float2*)(MEMB + (d*HALFW + p2)*RROWS + 2*rh2) = mv;

            *(float2*)(OUTB + isp(p2) + 2*rh2) = o;          // act_out -> [0,512)
            if (p2 < QUARTW) {
                float2 kv = *(const float2*)(S + isp(3*QUARTW + p2) + 2*rh2);
                *(float2*)(OUTB + isp(HALFW + p2) + 2*rh2) = kv;   // [768,1024)->[512,768)
            } else {
                int q  = p2 - QUARTW;
                int mi = g_recall[d*ACT_N + q];
                float2 rv = (mi >= d*HALFW)
                    ? *(const float2*)(S + isp(mi - d*HALFW) + 2*rh2)
                    : *(const float2*)(MEMB + mi*RROWS + 2*rh2);
                *(float2*)(OUTB + isp(3*QUARTW + q) + 2*rh2) = rv; // recall -> [768,1024)
            }
            cur ^= 1;
            __syncthreads();
        }
    }
    // 6 flips per depth x 8 depths -> cur = 0; sponge in buffer 0

    // ---- build pre = [mem[out_idx] (2048), sponge (1024)] in BF buffer 0 ----
    {
        float4 sv = *(const float4*)(sb + isp(t));   // whole sponge, 1 pos/thread
        __syncthreads();                             // reads done before clobber
        #pragma unroll
        for (int it = 0; it < 2; it++) {
            int pp = it*NTHREADS + t;
            int oi = g_outidx[pp];
            *(float4*)(sb + ibf(pp)) = *(const float4*)(MEMB + oi*RROWS);
        }
        __syncthreads();                             // mem reads done before tail clobbers
        *(float4*)(sb + ibf(2048 + t)) = sv;
        __syncthreads();
    }

    // ---- final 12-layer butterfly on 3072 as 6 fused double-layers (scalar, 3 slots) ----
    int rbB[3], wbB[3];
    #pragma unroll
    for (int j2 = 0; j2 < 3; j2++) {
        int u   = m + 256*j2;                    // unit in [0,768)
        int Ab  = (u >> 1) + (u & 1)*BF_HALF;
        rbB[j2] = ibf(Ab)   + r4;
        wbB[j2] = ibf(2*u)  + r4;
    }

    int c2 = 0;
    for (int s6 = 0; s6 < BF_DEPTH/2; s6++) {
        const float2* r0 = g_bfrot + (2*s6)*BF_HALF;
        const float4* r1 = (const float4*)(g_bfrot + (2*s6+1)*BF_HALF);
        const float* IN  = sb + c2*BF_STRIDE;
        float*       OUT = sb + (c2^1)*BF_STRIDE;
        #pragma unroll
        for (int j2 = 0; j2 < 3; j2++) {
            int u = m + 256*j2;
            float2 cs1 = r0[u];
            float2 cs2 = r0[u + BF_QUART];
            float4 co4 = r1[u];
            int rbs = rbB[j2], wbs = wbB[j2];

            float a1 = IN[rbs];
            float a2 = IN[rbs + BR1];
            float b1 = IN[rbs + BR2];
            float b2 = IN[rbs + BR3];
            float y1e = cs1.x*a1 + cs1.y*b1;
            float y1o = cs1.x*b1 - cs1.y*a1;
            float y2e = cs2.x*a2 + cs2.y*b2;
            float y2o = cs2.x*b2 - cs2.y*a2;
            OUT[wbs]       = co4.x*y1e + co4.y*y2e;
            OUT[wbs + BW1] = co4.z*y1o + co4.w*y2o;
            OUT[wbs + BW2] = co4.x*y2e - co4.y*y1e;
            OUT[wbs + BW3] = co4.z*y2o - co4.w*y1o;
        }
        c2 ^= 1;
        __syncthreads();
    }

    // result in buffer 0 (6 flips); emit first 512 columns
    if (t < HALFW) {
        float4 v = *(const float4*)(sb + ibf(t));
        out[(size_t)(row0 + 0)*HALFW + t] = v.x;
        out[(size_t)(row0 + 1)*HALFW + t] = v.y;
        out[(size_t)(row0 + 2)*HALFW + t] = v.z;
        out[(size_t)(row0 + 3)*HALFW + t] = v.w;
    }
}

extern "C" void kernel_launch(void* const* d_in, const int* in_sizes, int n_in,
                              void* d_out, int out_size)
{
    (void)in_sizes; (void)n_in; (void)out_size;
    const float* X          = (const float*)d_in[0];
    const float* scales     = (const float*)d_in[1];
    const float* angles     = (const float*)d_in[2];
    const float* act_bias   = (const float*)d_in[3];
    // d_in[4] = act_activation (unused by reference)
    const float* act_curv   = (const float*)d_in[5];
    const float* bf_angles  = (const float*)d_in[6];
    // d_in[7] = shuffle_perm (deterministic riffle, computed inline)
    const void*  recall_raw = d_in[8];
    const void*  out_raw    = d_in[9];
    // d_in[10] = bf_perm (deterministic riffle, computed inline)
    float* out = (float*)d_out;

    const int totalPrep = DEPTH_N*BDEPTH_N*HALFW + BF_DEPTH*BF_HALF + DEPTH_N*ACT_N;
    prep_kernel<<<(totalPrep + 255)/256, 256>>>(angles, bf_angles, act_bias, act_curv,
                                                recall_raw, out_raw);

    size_t smem = SMEM_FLOATS * sizeof(float);
    cudaFuncSetAttribute(sponge_kernel, cudaFuncAttributeMaxDynamicSharedMemorySize, (int)smem);
    sponge_kernel<<<NROWS/RROWS, NTHREADS, smem>>>(X, scales, out);
}

// round 12
// speedup vs baseline: 1.3401x; 1.3401x over previous
#include <cuda_runtime.h>

// ---------------- problem constants ----------------
#define NROWS     2048
#define RROWS     4          // batch rows per CTA (split 2+2 across thread row-halves)
#define NTHREADS  512
#define SPONGE_N  1024
#define HALFW     512
#define QUARTW    256
#define ACT_N     256
#define DEPTH_N   8
#define BDEPTH_N  10
#define BF_SIZE   3072
#define BF_HALF   1536
#define BF_QUART  768
#define BF_DEPTH  12

#define SP_STRIDE   4624                 // >= isp(1023)+4, 16B aligned
#define MEM_OFF     (2*SP_STRIDE)        // 9248
#define BF_STRIDE   13840                // >= ibf(3071)+4
#define SMEM_FLOATS (2*BF_STRIDE)        // 27680 floats = 110720 B -> 2 CTAs/SM

// ---------------- precomputed tables ----------------
__device__ __align__(16) float2 g_rot  [DEPTH_N*BDEPTH_N*HALFW];  // sponge (cos,sin)
__device__ __align__(16) float2 g_bfrot[BF_DEPTH*BF_HALF];        // final butterfly
__device__ float4 g_act  [DEPTH_N*ACT_N];           // (bias, c, t, 1/c)
__device__ int    g_recall[DEPTH_N*ACT_N];
__device__ int    g_outidx[2048];

__global__ void prep_kernel(const float* __restrict__ angles,
                            const float* __restrict__ bf_angles,
                            const float* __restrict__ act_bias,
                            const float* __restrict__ act_curv,
                            const void*  __restrict__ recall_raw,
                            const void*  __restrict__ out_raw)
{
    int i = blockIdx.x * blockDim.x + threadIdx.x;
    const int NROT = DEPTH_N*BDEPTH_N*HALFW;       // 40960
    const int NBF  = BF_DEPTH*BF_HALF;             // 18432
    if (i < NROT) {
        float s, c; sincosf(angles[i], &s, &c);
        g_rot[i] = make_float2(c, s);
    } else if (i < NROT + NBF) {
        int j = i - NROT;
        float s, c; sincosf(bf_angles[j], &s, &c);
        g_bfrot[j] = make_float2(c, s);
    } else if (i < NROT + NBF + DEPTH_N*ACT_N) {
        int k = i - NROT - NBF;
        float cu = act_curv[k];
        float c  = 0.5f*(cu + sqrtf(cu*cu + 1.0f));
        g_act[k] = make_float4(act_bias[k], c, 0.25f*3.14159265358979323846f/c, 1.0f/c);
    }
    // dtype-robust index decode (int32 vs int64)
    if (i < 2048) {
        const int* o32 = (const int*)out_raw;
        bool is64 = (o32[1]==0 && o32[3]==0 && o32[5]==0 && o32[7]==0);
        if (is64) {
            g_outidx[i] = (int)((const long long*)out_raw)[i];
            g_recall[i] = (int)((const long long*)recall_raw)[i];
        } else {
            g_outidx[i] = o32[i];
            g_recall[i] = ((const int*)recall_raw)[i];
        }
    }
}

// ---------------- padded shared-memory indexing ----------------
__device__ __forceinline__ int isp(int p) { return 4*p + ((p>>3)<<2) + ((p>>9)<<4); }
__device__ __forceinline__ int ibf(int p) { return 4*p + ((p>>3)<<2) + ((p>=1536)?16:0); }

// fixed offsets (verified constant across valid base positions; same as R5/R9)
#define SR1 576
#define SR2 1152
#define SR3 1728
#define SW1 4
#define SW2 2320
#define SW3 2324
#define BR1 1728
#define BR2 3456
#define BR3 5184
#define BW1 4
#define BW2 6928
#define BW3 6932

__device__ __forceinline__ float actf(float x, float c, float tt, float invc) {
    const float OOS2 = 0.70710678118654752f;
    float r = invc*(OOS2 - __cosf(0.78539816339744831f + c*x));
    if (x >  tt) r = invc*OOS2 + (x - tt);
    if (x < -tt) r = invc*(OOS2 - 1.0f);
    return r;
}

__device__ __forceinline__ float2 mix2(float c, float s, float2 a, float2 b) {
    return make_float2(c*a.x + s*b.x, c*a.y + s*b.y);
}

// coefficient prefetch for sponge stage s5 of depth block rotd
__device__ __forceinline__ void pf_sp(const float2* __restrict__ rotd, int s5, int m,
                                      float2& c1, float2& c2, float4& c4)
{
    const float2* r0 = rotd + (2*s5)*HALFW;
    c1 = __ldg(r0 + m);
    c2 = __ldg(r0 + m + QUARTW);
    c4 = __ldg((const float4*)(rotd + (2*s5+1)*HALFW) + m);
}

__global__ void __launch_bounds__(NTHREADS, 2)
sponge_kernel(const float* __restrict__ X,
              const float* __restrict__ scales,
              float* __restrict__ out)
{
    extern __shared__ float sb[];
    const int t    = threadIdx.x;
    const int row0 = blockIdx.x * RROWS;
    float* const MEMB = sb + MEM_OFF;

    // ---- load X * scales into sponge buffer 0 ----
    {
        float sc0 = scales[t], sc1 = scales[t + HALFW];
        int i0 = isp(t), i1 = i0 + SW2;
        #pragma unroll
        for (int r = 0; r < RROWS; r++) {
            const float* xr = X + (size_t)(row0 + r) * SPONGE_N;
            sb[i0 + r] = xr[t]         * sc0;
            sb[i1 + r] = xr[t + HALFW] * sc1;
        }
    }

    // ---- per-thread constants: thread = (pair m, row-half rh) ----
    const int  m   = t >> 1;
    const int  rh  = t & 1;
    const bool odd = rh;
    const int  A1  = (m >> 1) + (m & 1) * HALFW;
    const int  rb  = isp(A1)  + 2*rh;
    const int  wb  = isp(2*m) + 2*rh;
    const int  w0  = isp(t);
    const int  w1  = w0 + SW2;
    const int  ja  = t >> 1;
    const int  qa  = (t >= QUARTW) ? (t - QUARTW) : 0;   // recall slot (valid t>=256)

    // prime the coefficient pipeline: depth 0, stage 0
    float2 c1, c2; float4 c4;
    pf_sp(g_rot, 0, m, c1, c2, c4);
    float4 ap;  int mi = 0;

    __syncthreads();

    int cur = 0;
    for (int d = 0; d < DEPTH_N; d++) {
        const float2* rotd = g_rot + d*(BDEPTH_N*HALFW);
        // ---- 5 fused double-layer stages with prefetched coefficients ----
        #pragma unroll
        for (int s5 = 0; s5 < BDEPTH_N/2; s5++) {
            float2 u1 = c1, u2 = c2; float4 u4 = c4;
            // prefetch next stage's coefficients (or act params on last stage)
            if (s5 < BDEPTH_N/2 - 1) {
                pf_sp(rotd, s5+1, m, c1, c2, c4);
            } else {
                ap = g_act[d*ACT_N + ja];
                mi = __ldg(g_recall + d*ACT_N + qa);
            }
            const float* IN  = sb + cur*SP_STRIDE;
            float*       OUT = sb + (cur^1)*SP_STRIDE;

            float2 a1 = *(const float2*)(IN + rb);
            float2 a2 = *(const float2*)(IN + rb + SR1);
            float2 b1 = *(const float2*)(IN + rb + SR2);
            float2 b2 = *(const float2*)(IN + rb + SR3);
            float2 y1e = mix2(u1.x,  u1.y, a1, b1);
            float2 y1o = mix2(u1.x, -u1.y, b1, a1);
            float2 y2e = mix2(u2.x,  u2.y, a2, b2);
            float2 y2o = mix2(u2.x, -u2.y, b2, a2);
            *(float2*)(OUT + wb)       = mix2(u4.x,  u4.y, y1e, y2e);
            *(float2*)(OUT + wb + SW1) = mix2(u4.z,  u4.w, y1o, y2o);
            *(float2*)(OUT + wb + SW2) = mix2(u4.x, -u4.y, y2e, y1e);
            *(float2*)(OUT + wb + SW3) = mix2(u4.z, -u4.w, y2o, y1o);
            cur ^= 1;
            __syncthreads();
        }

        // ---- activation / mem store / recall: ONE barrier (R9-proven) ----
        {
            const float* S    = sb + cur*SP_STRIDE;
            float*       OUTB = sb + (cur^1)*SP_STRIDE;
            // prefetch next depth's stage-0 coefficients during this phase
            if (d < DEPTH_N-1) pf_sp(rotd + BDEPTH_N*HALFW, 0, m, c1, c2, c4);

            float4 x  = *(const float4*)(S + isp(HALFW + ja));
            float sg  = odd ? -1.0f : 1.0f;
            float4 o;
            o.x = actf(sg*(x.x + ap.x), ap.y, ap.z, ap.w);
            o.y = actf(sg*(x.y + ap.x), ap.y, ap.z, ap.w);
            o.z = actf(sg*(x.z + ap.x), ap.y, ap.z, ap.w);
            o.w = actf(sg*(x.w + ap.x), ap.y, ap.z, ap.w);

            float4 mv = *(const float4*)(S + w0);
            *(float4*)(MEMB + (d*HALFW + t)*RROWS) = mv;

            *(float4*)(OUTB + w0) = o;                        // act_out -> [0,512)
            if (t < QUARTW) {
                float4 kv = *(const float4*)(S + isp(3*QUARTW + t));
                *(float4*)(OUTB + isp(HALFW + t)) = kv;       // [768,1024)->[512,768)
            } else {
                float4 rv = (mi >= d*HALFW)
                    ? *(const float4*)(S + isp(mi - d*HALFW))
                    : *(const float4*)(MEMB + mi*RROWS);
                *(float4*)(OUTB + isp(3*QUARTW + qa)) = rv;   // recall -> [768,1024)
            }
            cur ^= 1;
            __syncthreads();
        }
    }
    // 6 flips per depth x 8 -> cur = 0; sponge in buffer 0

    // ---- build pre = [mem[out_idx] (2048), sponge (1024)] in BF buffer 0 ----
    {
        float4 s0 = *(const float4*)(sb + w0);
        float4 s1 = *(const float4*)(sb + w1);
        int oi0 = g_outidx[t];
        int oi1 = g_outidx[t + NTHREADS];
        int oi2 = g_outidx[t + 2*NTHREADS];
        int oi3 = g_outidx[t + 3*NTHREADS];
        __syncthreads();
        *(float4*)(sb + ibf(t))              = *(const float4*)(MEMB + oi0*RROWS);
        *(float4*)(sb + ibf(t + NTHREADS))   = *(const float4*)(MEMB + oi1*RROWS);
        *(float4*)(sb + ibf(t + 2*NTHREADS)) = *(const float4*)(MEMB + oi2*RROWS);
        *(float4*)(sb + ibf(t + 3*NTHREADS)) = *(const float4*)(MEMB + oi3*RROWS);
        __syncthreads();
        *(float4*)(sb + ibf(2048 + t))         = s0;
        *(float4*)(sb + ibf(2048 + HALFW + t)) = s1;
        __syncthreads();
    }

    // ---- final 12-layer butterfly as 6 fused double-layers, grouped coeff loads ----
    int rbB[3], wbB[3];
    #pragma unroll
    for (int j2 = 0; j2 < 3; j2++) {
        int pp  = m + 256*j2;
        int Ab  = (pp >> 1) + (pp & 1)*BF_HALF;
        rbB[j2] = ibf(Ab)    + 2*rh;
        wbB[j2] = ibf(2*pp)  + 2*rh;
    }

    int bcur = 0;
    for (int s6 = 0; s6 < BF_DEPTH/2; s6++) {
        const float2* r0 = g_bfrot + (2*s6)*BF_HALF;
        const float4* r1 = (const float4*)(g_bfrot + (2*s6+1)*BF_HALF);
        // group-load all 9 coefficient vectors FIRST (overlap with LDS below)
        float2 C1[3], C2[3]; float4 C4[3];
        #pragma unroll
        for (int j2 = 0; j2 < 3; j2++) {
            int pp = m + 256*j2;
            C1[j2] = __ldg(r0 + pp);
            C2[j2] = __ldg(r0 + pp + BF_QUART);
            C4[j2] = __ldg(r1 + pp);
        }
        const float* IN  = sb + bcur*BF_STRIDE;
        float*       OUT = sb + (bcur^1)*BF_STRIDE;
        #pragma unroll
        for (int j2 = 0; j2 < 3; j2++) {
            int rbs = rbB[j2], wbs = wbB[j2];
            float2 a1 = *(const float2*)(IN + rbs);
            float2 a2 = *(const float2*)(IN + rbs + BR1);
            float2 b1 = *(const float2*)(IN + rbs + BR2);
            float2 b2 = *(const float2*)(IN + rbs + BR3);
            float2 y1e = mix2(C1[j2].x,  C1[j2].y, a1, b1);
            float2 y1o = mix2(C1[j2].x, -C1[j2].y, b1, a1);
            float2 y2e = mix2(C2[j2].x,  C2[j2].y, a2, b2);
            float2 y2o = mix2(C2[j2].x, -C2[j2].y, b2, a2);
            *(float2*)(OUT + wbs)       = mix2(C4[j2].x,  C4[j2].y, y1e, y2e);
            *(float2*)(OUT + wbs + BW1) = mix2(C4[j2].z,  C4[j2].w, y1o, y2o);
            *(float2*)(OUT + wbs + BW2) = mix2(C4[j2].x, -C4[j2].y, y2e, y1e);
            *(float2*)(OUT + wbs + BW3) = mix2(C4[j2].z, -C4[j2].w, y2o, y1o);
        }
        bcur ^= 1;
        __syncthreads();
    }

    // result in buffer 0 (6 flips); emit first 512 columns
    {
        float4 v = *(const float4*)(sb + ibf(t));
        out[(size_t)(row0 + 0)*HALFW + t] = v.x;
        out[(size_t)(row0 + 1)*HALFW + t] = v.y;
        out[(size_t)(row0 + 2)*HALFW + t] = v.z;
        out[(size_t)(row0 + 3)*HALFW + t] = v.w;
    }
}

extern "C" void kernel_launch(void* const* d_in, const int* in_sizes, int n_in,
                              void* d_out, int out_size)
{
    (void)in_sizes; (void)n_in; (void)out_size;
    const float* X          = (const float*)d_in[0];
    const float* scales     = (const float*)d_in[1];
    const float* angles     = (const float*)d_in[2];
    const float* act_bias   = (const float*)d_in[3];
    // d_in[4] = act_activation (unused by reference)
    const float* act_curv   = (const float*)d_in[5];
    const float* bf_angles  = (const float*)d_in[6];
    // d_in[7] = shuffle_perm (deterministic riffle, computed inline)
    const void*  recall_raw = d_in[8];
    const void*  out_raw    = d_in[9];
    // d_in[10] = bf_perm (deterministic riffle, computed inline)
    float* out = (float*)d_out;

    const int totalPrep = DEPTH_N*BDEPTH_N*HALFW + BF_DEPTH*BF_HALF + DEPTH_N*ACT_N;
    prep_kernel<<<(totalPrep + 255)/256, 256>>>(angles, bf_angles, act_bias, act_curv,
                                                recall_raw, out_raw);

    size_t smem = SMEM_FLOATS * sizeof(float);
    cudaFuncSetAttribute(sponge_kernel, cudaFuncAttributeMaxDynamicSharedMemorySize, (int)smem);
    sponge_kernel<<<NROWS/RROWS, NTHREADS, smem>>>(X, scales, out);
}

// round 13
// speedup vs baseline: 1.3524x; 1.0091x over previous
#include <cuda_runtime.h>

// ---------------- problem constants ----------------
#define NROWS     2048
#define RROWS     4          // batch rows per CTA (split 2+2 across thread row-halves)
#define NTHREADS  512
#define SPONGE_N  1024
#define HALFW     512
#define QUARTW    256
#define ACT_N     256
#define DEPTH_N   8
#define BDEPTH_N  10
#define BF_SIZE   3072
#define BF_HALF   1536
#define BF_QUART  768
#define BF_DEPTH  12

#define SP_STRIDE   4624                 // >= isp(1023)+4, 16B aligned
#define MEM_OFF     (2*SP_STRIDE)        // 9248
#define BF_STRIDE   13840                // >= ibf(3071)+4
#define SMEM_FLOATS (2*BF_STRIDE)        // 27680 floats = 110720 B -> 2 CTAs/SM

// ---------------- precomputed tables ----------------
__device__ __align__(16) float2 g_rot  [DEPTH_N*BDEPTH_N*HALFW];  // sponge (cos,sin)
__device__ __align__(16) float2 g_bfrot[BF_DEPTH*BF_HALF];        // final butterfly
__device__ float4 g_act  [DEPTH_N*ACT_N];           // (bias, c, t, 1/c)
__device__ int    g_recall[DEPTH_N*ACT_N];
__device__ int    g_outidx[2048];

__global__ void prep_kernel(const float* __restrict__ angles,
                            const float* __restrict__ bf_angles,
                            const float* __restrict__ act_bias,
                            const float* __restrict__ act_curv,
                            const void*  __restrict__ recall_raw,
                            const void*  __restrict__ out_raw)
{
    int i = blockIdx.x * blockDim.x + threadIdx.x;
    const int NROT = DEPTH_N*BDEPTH_N*HALFW;       // 40960
    const int NBF  = BF_DEPTH*BF_HALF;             // 18432
    if (i < NROT) {
        float s, c; __sincosf(__ldg(angles + i), &s, &c);   // HW MUFU path
        g_rot[i] = make_float2(c, s);
    } else if (i < NROT + NBF) {
        int j = i - NROT;
        float s, c; __sincosf(__ldg(bf_angles + j), &s, &c);
        g_bfrot[j] = make_float2(c, s);
    } else if (i < NROT + NBF + DEPTH_N*ACT_N) {
        int k = i - NROT - NBF;
        float cu = __ldg(act_curv + k);
        float c  = 0.5f*(cu + sqrtf(cu*cu + 1.0f));
        g_act[k] = make_float4(__ldg(act_bias + k), c,
                               0.25f*3.14159265358979323846f/c, 1.0f/c);
    }
    // dtype-robust index decode (int32 vs int64)
    if (i < 2048) {
        const int* o32 = (const int*)out_raw;
        bool is64 = (o32[1]==0 && o32[3]==0 && o32[5]==0 && o32[7]==0);
        if (is64) {
            g_outidx[i] = (int)((const long long*)out_raw)[i];
            g_recall[i] = (int)((const long long*)recall_raw)[i];
        } else {
            g_outidx[i] = o32[i];
            g_recall[i] = ((const int*)recall_raw)[i];
        }
    }
}

// ---------------- padded shared-memory indexing ----------------
__device__ __forceinline__ int isp(int p) { return 4*p + ((p>>3)<<2) + ((p>>9)<<4); }
__device__ __forceinline__ int ibf(int p) { return 4*p + ((p>>3)<<2) + ((p>=1536)?16:0); }

// fixed offsets (verified constant across valid base positions; same as R5/R9)
#define SR1 576
#define SR2 1152
#define SR3 1728
#define SW1 4
#define SW2 2320
#define SW3 2324
#define BR1 1728
#define BR2 3456
#define BR3 5184
#define BW1 4
#define BW2 6928
#define BW3 6932

__device__ __forceinline__ float actf(float x, float c, float tt, float invc) {
    const float OOS2 = 0.70710678118654752f;
    float r = invc*(OOS2 - __cosf(0.78539816339744831f + c*x));
    if (x >  tt) r = invc*OOS2 + (x - tt);
    if (x < -tt) r = invc*(OOS2 - 1.0f);
    return r;
}

__device__ __forceinline__ float2 mix2(float c, float s, float2 a, float2 b) {
    return make_float2(c*a.x + s*b.x, c*a.y + s*b.y);
}

// coefficient prefetch for sponge stage s5 of depth block rotd
__device__ __forceinline__ void pf_sp(const float2* __restrict__ rotd, int s5, int m,
                                      float2& c1, float2& c2, float4& c4)
{
    const float2* r0 = rotd + (2*s5)*HALFW;
    c1 = __ldg(r0 + m);
    c2 = __ldg(r0 + m + QUARTW);
    c4 = __ldg((const float4*)(rotd + (2*s5+1)*HALFW) + m);
}

__global__ void __launch_bounds__(NTHREADS, 2)
sponge_kernel(const float* __restrict__ X,
              const float* __restrict__ scales,
              float* __restrict__ out)
{
    extern __shared__ float sb[];
    const int t    = threadIdx.x;
    const int row0 = blockIdx.x * RROWS;
    float* const MEMB = sb + MEM_OFF;

    // ---- load X * scales into sponge buffer 0 ----
    {
        float sc0 = scales[t], sc1 = scales[t + HALFW];
        int i0 = isp(t), i1 = i0 + SW2;
        #pragma unroll
        for (int r = 0; r < RROWS; r++) {
            const float* xr = X + (size_t)(row0 + r) * SPONGE_N;
            sb[i0 + r] = xr[t]         * sc0;
            sb[i1 + r] = xr[t + HALFW] * sc1;
        }
    }

    // ---- per-thread constants: thread = (pair m, row-half rh) ----
    const int  m   = t >> 1;
    const int  rh  = t & 1;
    const bool odd = rh;
    const int  A1  = (m >> 1) + (m & 1) * HALFW;
    const int  rb  = isp(A1)  + 2*rh;
    const int  wb  = isp(2*m) + 2*rh;
    const int  w0  = isp(t);
    const int  w1  = w0 + SW2;
    const int  ja  = t >> 1;
    const int  qa  = (t >= QUARTW) ? (t - QUARTW) : 0;   // recall slot (valid t>=256)

    // prime the coefficient pipeline: depth 0, stage 0
    float2 c1, c2; float4 c4;
    pf_sp(g_rot, 0, m, c1, c2, c4);
    float4 ap;  int mi = 0;

    __syncthreads();

    int cur = 0;
    for (int d = 0; d < DEPTH_N; d++) {
        const float2* rotd = g_rot + d*(BDEPTH_N*HALFW);
        // ---- 5 fused double-layer stages with prefetched coefficients ----
        #pragma unroll
        for (int s5 = 0; s5 < BDEPTH_N/2; s5++) {
            float2 u1 = c1, u2 = c2; float4 u4 = c4;
            // prefetch next stage's coefficients (or act params on last stage)
            if (s5 < BDEPTH_N/2 - 1) {
                pf_sp(rotd, s5+1, m, c1, c2, c4);
            } else {
                ap = g_act[d*ACT_N + ja];
                mi = __ldg(g_recall + d*ACT_N + qa);
            }
            const float* IN  = sb + cur*SP_STRIDE;
            float*       OUT = sb + (cur^1)*SP_STRIDE;

            float2 a1 = *(const float2*)(IN + rb);
            float2 a2 = *(const float2*)(IN + rb + SR1);
            float2 b1 = *(const float2*)(IN + rb + SR2);
            float2 b2 = *(const float2*)(IN + rb + SR3);
            float2 y1e = mix2(u1.x,  u1.y, a1, b1);
            float2 y1o = mix2(u1.x, -u1.y, b1, a1);
            float2 y2e = mix2(u2.x,  u2.y, a2, b2);
            float2 y2o = mix2(u2.x, -u2.y, b2, a2);
            *(float2*)(OUT + wb)       = mix2(u4.x,  u4.y, y1e, y2e);
            *(float2*)(OUT + wb + SW1) = mix2(u4.z,  u4.w, y1o, y2o);
            *(float2*)(OUT + wb + SW2) = mix2(u4.x, -u4.y, y2e, y1e);
            *(float2*)(OUT + wb + SW3) = mix2(u4.z, -u4.w, y2o, y1o);
            cur ^= 1;
            __syncthreads();
        }

        // ---- activation / mem store / recall: ONE barrier (R9-proven) ----
        {
            const float* S    = sb + cur*SP_STRIDE;
            float*       OUTB = sb + (cur^1)*SP_STRIDE;
            // prefetch next depth's stage-0 coefficients during this phase
            if (d < DEPTH_N-1) pf_sp(rotd + BDEPTH_N*HALFW, 0, m, c1, c2, c4);

            float4 x  = *(const float4*)(S + isp(HALFW + ja));
            float sg  = odd ? -1.0f : 1.0f;
            float4 o;
            o.x = actf(sg*(x.x + ap.x), ap.y, ap.z, ap.w);
            o.y = actf(sg*(x.y + ap.x), ap.y, ap.z, ap.w);
            o.z = actf(sg*(x.z + ap.x), ap.y, ap.z, ap.w);
            o.w = actf(sg*(x.w + ap.x), ap.y, ap.z, ap.w);

            float4 mv = *(const float4*)(S + w0);
            *(float4*)(MEMB + (d*HALFW + t)*RROWS) = mv;

            *(float4*)(OUTB + w0) = o;                        // act_out -> [0,512)
            if (t < QUARTW) {
                float4 kv = *(const float4*)(S + isp(3*QUARTW + t));
                *(float4*)(OUTB + isp(HALFW + t)) = kv;       // [768,1024)->[512,768)
            } else {
                float4 rv = (mi >= d*HALFW)
                    ? *(const float4*)(S + isp(mi - d*HALFW))
                    : *(const float4*)(MEMB + mi*RROWS);
                *(float4*)(OUTB + isp(3*QUARTW + qa)) = rv;   // recall -> [768,1024)
            }
            cur ^= 1;
            __syncthreads();
        }
    }
    // 6 flips per depth x 8 -> cur = 0; sponge in buffer 0

    // ---- build pre = [mem[out_idx] (2048), sponge (1024)] in BF buffer 0 ----
    {
        float4 s0 = *(const float4*)(sb + w0);
        float4 s1 = *(const float4*)(sb + w1);
        int oi0 = g_outidx[t];
        int oi1 = g_outidx[t + NTHREADS];
        int oi2 = g_outidx[t + 2*NTHREADS];
        int oi3 = g_outidx[t + 3*NTHREADS];
        __syncthreads();
        *(float4*)(sb + ibf(t))              = *(const float4*)(MEMB + oi0*RROWS);
        *(float4*)(sb + ibf(t + NTHREADS))   = *(const float4*)(MEMB + oi1*RROWS);
        *(float4*)(sb + ibf(t + 2*NTHREADS)) = *(const float4*)(MEMB + oi2*RROWS);
        *(float4*)(sb + ibf(t + 3*NTHREADS)) = *(const float4*)(MEMB + oi3*RROWS);
        __syncthreads();
        *(float4*)(sb + ibf(2048 + t))         = s0;
        *(float4*)(sb + ibf(2048 + HALFW + t)) = s1;
        __syncthreads();
    }

    // ---- final 12-layer butterfly as 6 fused double-layers, grouped coeff loads ----
    int rbB[3], wbB[3];
    #pragma unroll
    for (int j2 = 0; j2 < 3; j2++) {
        int pp  = m + 256*j2;
        int Ab  = (pp >> 1) + (pp & 1)*BF_HALF;
        rbB[j2] = ibf(Ab)    + 2*rh;
        wbB[j2] = ibf(2*pp)  + 2*rh;
    }

    int bcur = 0;
    for (int s6 = 0; s6 < BF_DEPTH/2; s6++) {
        const float2* r0 = g_bfrot + (2*s6)*BF_HALF;
        const float4* r1 = (const float4*)(g_bfrot + (2*s6+1)*BF_HALF);
        // group-load all 9 coefficient vectors FIRST (overlap with LDS below)
        float2 C1[3], C2[3]; float4 C4[3];
        #pragma unroll
        for (int j2 = 0; j2 < 3; j2++) {
            int pp = m + 256*j2;
            C1[j2] = __ldg(r0 + pp);
            C2[j2] = __ldg(r0 + pp + BF_QUART);
            C4[j2] = __ldg(r1 + pp);
        }
        const float* IN  = sb + bcur*BF_STRIDE;
        float*       OUT = sb + (bcur^1)*BF_STRIDE;
        #pragma unroll
        for (int j2 = 0; j2 < 3; j2++) {
            int rbs = rbB[j2], wbs = wbB[j2];
            float2 a1 = *(const float2*)(IN + rbs);
            float2 a2 = *(const float2*)(IN + rbs + BR1);
            float2 b1 = *(const float2*)(IN + rbs + BR2);
            float2 b2 = *(const float2*)(IN + rbs + BR3);
            float2 y1e = mix2(C1[j2].x,  C1[j2].y, a1, b1);
            float2 y1o = mix2(C1[j2].x, -C1[j2].y, b1, a1);
            float2 y2e = mix2(C2[j2].x,  C2[j2].y, a2, b2);
            float2 y2o = mix2(C2[j2].x, -C2[j2].y, b2, a2);
            *(float2*)(OUT + wbs)       = mix2(C4[j2].x,  C4[j2].y, y1e, y2e);
            *(float2*)(OUT + wbs + BW1) = mix2(C4[j2].z,  C4[j2].w, y1o, y2o);
            *(float2*)(OUT + wbs + BW2) = mix2(C4[j2].x, -C4[j2].y, y2e, y1e);
            *(float2*)(OUT + wbs + BW3) = mix2(C4[j2].z, -C4[j2].w, y2o, y1o);
        }
        bcur ^= 1;
        __syncthreads();
    }

    // result in buffer 0 (6 flips); emit first 512 columns
    {
        float4 v = *(const float4*)(sb + ibf(t));
        out[(size_t)(row0 + 0)*HALFW + t] = v.x;
        out[(size_t)(row0 + 1)*HALFW + t] = v.y;
        out[(size_t)(row0 + 2)*HALFW + t] = v.z;
        out[(size_t)(row0 + 3)*HALFW + t] = v.w;
    }
}

extern "C" void kernel_launch(void* const* d_in, const int* in_sizes, int n_in,
                              void* d_out, int out_size)
{
    (void)in_sizes; (void)n_in; (void)out_size;
    const float* X          = (const float*)d_in[0];
    const float* scales     = (const float*)d_in[1];
    const float* angles     = (const float*)d_in[2];
    const float* act_bias   = (const float*)d_in[3];
    // d_in[4] = act_activation (unused by reference)
    const float* act_curv   = (const float*)d_in[5];
    const float* bf_angles  = (const float*)d_in[6];
    // d_in[7] = shuffle_perm (deterministic riffle, computed inline)
    const void*  recall_raw = d_in[8];
    const void*  out_raw    = d_in[9];
    // d_in[10] = bf_perm (deterministic riffle, computed inline)
    float* out = (float*)d_out;

    const int totalPrep = DEPTH_N*BDEPTH_N*HALFW + BF_DEPTH*BF_HALF + DEPTH_N*ACT_N;
    prep_kernel<<<(totalPrep + 511)/512, 512>>>(angles, bf_angles, act_bias, act_curv,
                                                recall_raw, out_raw);

    size_t smem = SMEM_FLOATS * sizeof(float);
    cudaFuncSetAttribute(sponge_kernel, cudaFuncAttributeMaxDynamicSharedMemorySize, (int)smem);
    sponge_kernel<<<NROWS/RROWS, NTHREADS, smem>>>(X, scales, out);
}